// round 15
// baseline (speedup 1.0000x reference)
#include <cuda_runtime.h>
#include <math.h>

#define NB 256      // batch / steps
#define ND 512      // D
#define NH 2048     // H
#define NS 32768    // slots
#define RSPLIT 32
#define CMAX 4096
#define CCAP 1024
#define RC 8192     // R0-candidate array stride
#define RCAPT 6144  // R0-candidate soft cap
#define SEG (NS / 256)   // 128 elements per thread in prep pass B

// ---------------- static device scratch ----------------
__device__ float g_K[NB * ND];
__device__ float g_WV[NB * ND];
__device__ float g_G[NB * NB];
__device__ float g_E[NB * NS];              // raw scores
__device__ float g_m[NB];
__device__ float g_part[RSPLIT * NB * ND];  // split-K scratch
__device__ int   g_slots[NB];
__device__ float g_merged[NB * 2 * ND];
__device__ float g_H1[NB * NH];
__device__ unsigned long long g_cand[(size_t)NB * CMAX];  // argmax candidates (key|~idx)
__device__ int g_cand_n[NB];
__device__ unsigned int g_rcand[(size_t)NB * RC];         // sparse-softmax indices
__device__ int g_rcand_n[NB];

__device__ __forceinline__ unsigned int fkey(float f) {
    unsigned int u = __float_as_uint(f);
    return u ^ (((unsigned int)((int)u >> 31)) | 0x80000000u);
}

// packed fp32x2 helpers (sm_103a FFMA2 — PTX-only path)
__device__ __forceinline__ void ffma2(unsigned long long& d, unsigned long long a,
                                      unsigned long long b) {
    asm("fma.rn.f32x2 %0, %1, %2, %0;" : "+l"(d) : "l"(a), "l"(b));
}
__device__ __forceinline__ unsigned long long bcast2(float x) {
    unsigned long long r;
    unsigned int u = __float_as_uint(x);
    asm("mov.b64 %0, {%1, %1};" : "=l"(r) : "r"(u));
    return r;
}
__device__ __forceinline__ float2 unpack2(unsigned long long v) {
    float2 f;
    asm("mov.b64 {%0, %1}, %2;" : "=f"(f.x), "=f"(f.y) : "l"(v));
    return f;
}

// ---------------- split-K 64x64 NT GEMM ----------------
__global__ void __launch_bounds__(256) splitk_nt(
    const float* __restrict__ A, const float* __restrict__ B, float* __restrict__ outP,
    int N, int ldA, int ldB, int kchunk)
{
    __shared__ __align__(16) float As[16][68];
    __shared__ __align__(16) float Bs[16][68];
    const int tid = threadIdx.x;
    const int tx = tid & 15, ty = tid >> 4;
    const int bm0 = blockIdx.y * 64, bn0 = blockIdx.x * 64;
    const int kbase = blockIdx.z * kchunk;
    const int M = gridDim.y * 64;
    const int lr = tid >> 2;
    const int lq = (tid & 3) * 4;
    const float* Ap = A + (size_t)(bm0 + lr) * ldA + kbase + lq;
    const float* Bp = B + (size_t)(bn0 + lr) * ldB + kbase + lq;
    unsigned long long acc2[4][2] = {};
    for (int k0 = 0; k0 < kchunk; k0 += 16) {
        float4 av = *(const float4*)(Ap + k0);
        float4 bv = *(const float4*)(Bp + k0);
        __syncthreads();
        As[lq + 0][lr] = av.x; As[lq + 1][lr] = av.y;
        As[lq + 2][lr] = av.z; As[lq + 3][lr] = av.w;
        Bs[lq + 0][lr] = bv.x; Bs[lq + 1][lr] = bv.y;
        Bs[lq + 2][lr] = bv.z; Bs[lq + 3][lr] = bv.w;
        __syncthreads();
        #pragma unroll
        for (int k = 0; k < 16; k++) {
            float4 a = *(const float4*)&As[k][ty * 4];
            ulonglong2 b = *(const ulonglong2*)&Bs[k][tx * 4];
            float ar[4] = {a.x, a.y, a.z, a.w};
            #pragma unroll
            for (int m = 0; m < 4; m++) {
                unsigned long long am = bcast2(ar[m]);
                ffma2(acc2[m][0], am, b.x);
                ffma2(acc2[m][1], am, b.y);
            }
        }
    }
    float* out = outP + (size_t)blockIdx.z * M * N;
    #pragma unroll
    for (int a = 0; a < 4; a++) {
        float2 p0 = unpack2(acc2[a][0]);
        float2 p1 = unpack2(acc2[a][1]);
        *(float4*)&out[(size_t)(bm0 + ty * 4 + a) * N + bn0 + tx * 4] =
            make_float4(p0.x, p0.y, p1.x, p1.y);
    }
}

// ---------------- reduce split-K partials ----------------
__global__ void __launch_bounds__(256) reduce_kernel(
    const float* __restrict__ part, float* __restrict__ C,
    const float* __restrict__ bias, int MN, int N, int Z, int doRelu)
{
    const int q = blockIdx.x * 256 + threadIdx.x;
    if (q * 4 >= MN) return;
    float4 s = *(const float4*)&part[q * 4];
    for (int z = 1; z < Z; z++) {
        float4 v = *(const float4*)&part[(size_t)z * MN + q * 4];
        s.x += v.x; s.y += v.y; s.z += v.z; s.w += v.w;
    }
    if (bias) {
        float4 b = *(const float4*)&bias[(q * 4) % N];
        s.x += b.x; s.y += b.y; s.z += b.z; s.w += b.w;
    }
    if (doRelu) {
        s.x = fmaxf(s.x, 0.f); s.y = fmaxf(s.y, 0.f);
        s.z = fmaxf(s.z, 0.f); s.w = fmaxf(s.w, 0.f);
    }
    *(float4*)&C[q * 4] = s;
}

// ---------------- 128x128 tile NT GEMM (packed, double-buffered) ----------------
#define FMA8x8P(kk)                                                             \
    {                                                                           \
        float4 t0 = *(const float4*)&As[buf][kk][ty * 4];                       \
        float4 t1 = *(const float4*)&As[buf][kk][ty * 4 + 64];                  \
        ulonglong2 b01 = *(const ulonglong2*)&Bs[buf][kk][tx * 4];              \
        ulonglong2 b23 = *(const ulonglong2*)&Bs[buf][kk][tx * 4 + 64];         \
        float ar[8] = {t0.x, t0.y, t0.z, t0.w, t1.x, t1.y, t1.z, t1.w};         \
        _Pragma("unroll")                                                       \
        for (int m = 0; m < 8; m++) {                                           \
            unsigned long long am = bcast2(ar[m]);                              \
            ffma2(acc2[m][0], am, b01.x);                                       \
            ffma2(acc2[m][1], am, b01.y);                                       \
            ffma2(acc2[m][2], am, b23.x);                                       \
            ffma2(acc2[m][3], am, b23.y);                                       \
        }                                                                       \
    }

__global__ void __launch_bounds__(256) gemm_nt_128(
    const float* __restrict__ A, const float* __restrict__ B, float* __restrict__ C,
    int N, int Kd)
{
    __shared__ __align__(16) float As[2][8][136];
    __shared__ __align__(16) float Bs[2][8][136];
    const int tid = threadIdx.x;
    const int bm0 = blockIdx.y * 128, bn0 = blockIdx.x * 128;
    const int lr = tid >> 1;
    const int lk = (tid & 1) * 4;
    const float* Ap = A + (size_t)(bm0 + lr) * Kd + lk;
    const float* Bp = B + (size_t)(bn0 + lr) * Kd + lk;
    const int tx = tid & 15, ty = tid >> 4;
    unsigned long long acc2[8][4] = {};
    int buf = 0;
    {
        float4 a = *(const float4*)Ap;
        float4 b = *(const float4*)Bp;
        As[0][lk + 0][lr] = a.x; As[0][lk + 1][lr] = a.y;
        As[0][lk + 2][lr] = a.z; As[0][lk + 3][lr] = a.w;
        Bs[0][lk + 0][lr] = b.x; Bs[0][lk + 1][lr] = b.y;
        Bs[0][lk + 2][lr] = b.z; Bs[0][lk + 3][lr] = b.w;
    }
    __syncthreads();
    for (int k0 = 8; k0 <= Kd; k0 += 8) {
        float4 an, bn;
        if (k0 < Kd) {
            an = *(const float4*)(Ap + k0);
            bn = *(const float4*)(Bp + k0);
        }
        #pragma unroll
        for (int kk = 0; kk < 8; kk++) FMA8x8P(kk)
        if (k0 < Kd) {
            buf ^= 1;
            As[buf][lk + 0][lr] = an.x; As[buf][lk + 1][lr] = an.y;
            As[buf][lk + 2][lr] = an.z; As[buf][lk + 3][lr] = an.w;
            Bs[buf][lk + 0][lr] = bn.x; Bs[buf][lk + 1][lr] = bn.y;
            Bs[buf][lk + 2][lr] = bn.z; Bs[buf][lk + 3][lr] = bn.w;
            __syncthreads();
        }
    }
    #pragma unroll
    for (int m = 0; m < 8; m++) {
        int r = bm0 + ty * 4 + (m & 3) + (m >> 2) * 64;
        float2 p0 = unpack2(acc2[m][0]);
        float2 p1 = unpack2(acc2[m][1]);
        float2 p2 = unpack2(acc2[m][2]);
        float2 p3 = unpack2(acc2[m][3]);
        *(float4*)&C[(size_t)r * N + bn0 + tx * 4] = make_float4(p0.x, p0.y, p1.x, p1.y);
        *(float4*)&C[(size_t)r * N + bn0 + tx * 4 + 64] = make_float4(p2.x, p2.y, p3.x, p3.y);
    }
}

// ---------------- prep: hist+max, thresholds, segment compaction (no exp) ----------------
__global__ void __launch_bounds__(256) prep_kernel()
{
    const int i = blockIdx.x;
    const int tid = threadIdx.x;
    const int lane = tid & 31, wid = tid >> 5;
    __shared__ unsigned int hist[4096];
    __shared__ float red[256];
    __shared__ unsigned int csum[256];
    __shared__ unsigned int winc[8];
    __shared__ int s_thr1, s_thr2;
    for (int q = tid; q < 4096; q += 256) hist[q] = 0;
    __syncthreads();
    const float4* row = (const float4*)(g_E + (size_t)i * NS);
    float mx = -1e30f;
    for (int q = tid; q < NS / 4; q += 256) {
        float4 v = row[q];
        atomicAdd(&hist[fkey(v.x) >> 20], 1u);
        atomicAdd(&hist[fkey(v.y) >> 20], 1u);
        atomicAdd(&hist[fkey(v.z) >> 20], 1u);
        atomicAdd(&hist[fkey(v.w) >> 20], 1u);
        mx = fmaxf(mx, fmaxf(fmaxf(v.x, v.y), fmaxf(v.z, v.w)));
    }
    red[tid] = mx;
    __syncthreads();
    for (int s = 128; s; s >>= 1) {
        if (tid < s) red[tid] = fmaxf(red[tid], red[tid + s]);
        __syncthreads();
    }
    const float m = red[0];
    __syncthreads();
    if (tid == 0) g_m[i] = m;
    unsigned int gs = 0;
    #pragma unroll
    for (int b = 0; b < 16; b++) gs += hist[tid * 16 + b];
    csum[tid] = gs;
    __syncthreads();
    if (tid == 0) {
        unsigned int run = 0;
        int c = 255;
        for (; c > 0; c--) { if (run + csum[c] >= 256u) break; run += csum[c]; }
        int b = c * 16 + 15;
        for (; b > c * 16; b--) { run += hist[b]; if (run >= 256u) break; }
        s_thr1 = b;
        int bv = (int)(fkey(m - 20.0f) >> 20);
        int gv = bv >> 4;
        unsigned int S = 0;
        for (int g2 = gv + 1; g2 < 256; g2++) S += csum[g2];
        int gend = gv * 16 + 15;
        for (int b2 = bv; b2 <= gend; b2++) S += hist[b2];
        if (S <= (unsigned)RCAPT) {
            s_thr2 = bv;
        } else {
            unsigned int r3 = 0;
            int c3 = 255;
            for (; c3 > 0; c3--) { if (r3 + csum[c3] >= (unsigned)RCAPT) break; r3 += csum[c3]; }
            int b3 = c3 * 16 + 15;
            for (; b3 > c3 * 16; b3--) { r3 += hist[b3]; if (r3 >= (unsigned)RCAPT) break; }
            s_thr2 = b3;
        }
    }
    __syncthreads();
    const unsigned int t1 = ((unsigned int)s_thr1) << 20;
    const unsigned int t2 = ((unsigned int)s_thr2) << 20;
    // pass B: per-thread contiguous segment; count, one block scan, write
    const float* erow = g_E + (size_t)i * NS;
    const int base = tid * SEG;
    unsigned int c1 = 0, c2 = 0;
    #pragma unroll 4
    for (int k = 0; k < SEG; k += 4) {
        float4 v = *(const float4*)(erow + base + k);
        unsigned int kk[4] = {fkey(v.x), fkey(v.y), fkey(v.z), fkey(v.w)};
        #pragma unroll
        for (int u = 0; u < 4; u++) {
            c1 += (kk[u] >= t1);
            c2 += (kk[u] >= t2);
        }
    }
    unsigned int pack = c1 | (c2 << 16);
    unsigned int x = pack;
    #pragma unroll
    for (int off = 1; off < 32; off <<= 1) {
        unsigned int y = __shfl_up_sync(0xffffffffu, x, off);
        if (lane >= off) x += y;
    }
    if (lane == 31) winc[wid] = x;
    __syncthreads();
    if (tid < 8) {
        unsigned int xx = winc[tid];
        #pragma unroll
        for (int off = 1; off < 8; off <<= 1) {
            unsigned int y = __shfl_up_sync(0xffu, xx, off);
            if (tid >= off) xx += y;
        }
        winc[tid] = xx;
    }
    __syncthreads();
    unsigned int wb = (wid == 0) ? 0u : winc[wid - 1];
    unsigned int excl = x - pack + wb;
    int o1 = (int)(excl & 0xffffu);
    int o2 = (int)(excl >> 16);
    unsigned long long* cd = g_cand + (size_t)i * CMAX;
    unsigned int* rd = g_rcand + (size_t)i * RC;
    for (int k = 0; k < SEG; k += 4) {
        float4 v = *(const float4*)(erow + base + k);
        unsigned int kk[4] = {fkey(v.x), fkey(v.y), fkey(v.z), fkey(v.w)};
        #pragma unroll
        for (int u = 0; u < 4; u++) {
            const int j = base + k + u;
            if (kk[u] >= t1) {
                if (o1 < CMAX)
                    cd[o1] = ((unsigned long long)kk[u] << 32) | (unsigned int)(~j);
                o1++;
            }
            if (kk[u] >= t2) {
                if (o2 < RC) rd[o2] = (unsigned int)j;
                o2++;
            }
        }
    }
    if (tid == 255) {
        int n1 = (int)(x & 0xffffu) + (int)(wb & 0xffffu);
        int n2 = (int)(x >> 16) + (int)(wb >> 16);
        g_cand_n[i] = n1 < CMAX ? n1 : CMAX;
        g_rcand_n[i] = n2 < RC ? n2 : RC;
    }
}

// ---------------- sequential argmax chain: single warp, no block syncs ----------------
__global__ void __launch_bounds__(32) seq_kernel()
{
    __shared__ unsigned int mask[NS / 32];
    __shared__ unsigned long long cbuf[2][CCAP];
    __shared__ float grow[2][NB];
    __shared__ int cnArr[NB];
    __shared__ int slotArr[NB];
    __shared__ int writerArr[NB];
    const int lane = threadIdx.x;
    for (int q = lane; q < NS / 32; q += 32) mask[q] = 0u;
    for (int q = lane; q < NB; q += 32) cnArr[q] = g_cand_n[q];
    __syncwarp();
    int cnt = 0;   // uniform across lanes
    {
        int lim = cnArr[0] < CCAP ? cnArr[0] : CCAP;
        for (int q = lane; q < lim; q += 32) cbuf[0][q] = g_cand[q];
        for (int q = lane; q < NB; q += 32) grow[0][q] = g_G[q];
    }
    __syncwarp();
    for (int i = 0; i < NB; i++) {
        const int buf = i & 1, nxt = buf ^ 1;
        unsigned long long pc[CCAP / 32];
        float pg[NB / 32];
        int limN = 0;
        if (i + 1 < NB) {
            int cnN = cnArr[i + 1];
            limN = cnN < CCAP ? cnN : CCAP;
            #pragma unroll
            for (int k = 0; k < NB / 32; k++)
                pg[k] = g_G[(i + 1) * NB + lane + k * 32];
            #pragma unroll
            for (int k = 0; k < CCAP / 32; k++) {
                int idx = lane + k * 32;
                pc[k] = (idx < limN) ? g_cand[(size_t)(i + 1) * CMAX + idx] : 0ull;
            }
        }
        const int cn = cnArr[i];
        unsigned long long best = 0ull;
        for (int q = lane; q < cn; q += 32) {
            unsigned long long p = (q < CCAP) ? cbuf[buf][q]
                                              : g_cand[(size_t)i * CMAX + q];
            unsigned int idx = ~(unsigned int)p;
            if (!((mask[idx >> 5] >> (idx & 31)) & 1u))
                best = best > p ? best : p;
        }
        for (int t = lane; t < cnt; t += 32) {
            float g = grow[buf][writerArr[t]];
            unsigned long long p =
                ((unsigned long long)fkey(g) << 32) | (unsigned int)(~slotArr[t]);
            best = best > p ? best : p;
        }
        #pragma unroll
        for (int off = 16; off; off >>= 1) {
            unsigned long long o = __shfl_down_sync(0xffffffffu, best, off);
            best = best > o ? best : o;
        }
        best = __shfl_sync(0xffffffffu, best, 0);
        const int sb = (int)(~(unsigned int)best);
        int found = -1;
        for (int t = lane; t < cnt; t += 32)
            if (slotArr[t] == sb) found = t;
        #pragma unroll
        for (int off = 16; off; off >>= 1) {
            int o = __shfl_down_sync(0xffffffffu, found, off);
            found = found > o ? found : o;
        }
        found = __shfl_sync(0xffffffffu, found, 0);
        if (lane == 0) {
            g_slots[i] = sb;
            if (found >= 0) writerArr[found] = i;
            else { slotArr[cnt] = sb; writerArr[cnt] = i; }
            mask[sb >> 5] |= (1u << (sb & 31));
        }
        if (found < 0) cnt++;
        if (i + 1 < NB) {
            #pragma unroll
            for (int k = 0; k < NB / 32; k++)
                grow[nxt][lane + k * 32] = pg[k];
            #pragma unroll
            for (int k = 0; k < CCAP / 32; k++) {
                int idx = lane + k * 32;
                if (idx < limN) cbuf[nxt][idx] = pc[k];
            }
        }
        __syncwarp();
    }
}

// ---------------- passB: sparse softmax (weights+Z) + corrections + merge ----------------
__global__ void __launch_bounds__(512) passB_kernel(const float* __restrict__ S,
                                                    const float* __restrict__ MV)
{
    const int i = blockIdx.x;
    const int tid = threadIdx.x;
    __shared__ int sl[NB];
    __shared__ float e0s[NB], e1s[NB], zar[NB];
    __shared__ unsigned char lastf[NB];
    __shared__ unsigned int sidx[512];
    __shared__ float sw[512];
    __shared__ float zred[512];
    if (tid < NB) sl[tid] = g_slots[tid];
    __syncthreads();
    const float mi = g_m[i];
    const float* Erow = g_E + (size_t)i * NS;
    if (tid < NB) {
        float z = 0.f;
        unsigned char lf = 0;
        if (tid < i) {
            const int t = tid;
            const int s = sl[t];
            bool last = true;
            for (int t2 = t + 1; t2 < i; t2++)
                if (sl[t2] == s) { last = false; break; }
            if (last) {
                lf = 1;
                const float e0 = __expf(Erow[s] - mi);
                const float e1 = __expf(g_G[i * NB + t] - mi);
                e0s[t] = e0; e1s[t] = e1;
                z = e1 - e0;
            }
        }
        lastf[tid] = lf;
        zar[tid] = z;
    }
    __syncthreads();
    for (int s = 128; s; s >>= 1) {
        if (tid < s) zar[tid] += zar[tid + s];
        __syncthreads();
    }
    const float zcorr = zar[0];
    const int d = tid;
    const int rn = g_rcand_n[i];
    const unsigned int* rlist = g_rcand + (size_t)i * RC;
    float a0 = 0.f, a1 = 0.f, a2 = 0.f, a3 = 0.f;
    float zacc = 0.f;
    for (int st = 0; st < rn; st += 512) {
        const int nst = (rn - st) < 512 ? (rn - st) : 512;
        __syncthreads();
        if (tid < nst) {
            unsigned int j = rlist[st + tid];
            float w = __expf(Erow[j] - mi);
            sidx[tid] = j;
            sw[tid] = w;
            zacc += w;
        }
        __syncthreads();
        int t = 0;
        for (; t + 4 <= nst; t += 4) {
            a0 += sw[t + 0] * MV[(size_t)sidx[t + 0] * ND + d];
            a1 += sw[t + 1] * MV[(size_t)sidx[t + 1] * ND + d];
            a2 += sw[t + 2] * MV[(size_t)sidx[t + 2] * ND + d];
            a3 += sw[t + 3] * MV[(size_t)sidx[t + 3] * ND + d];
        }
        for (; t < nst; t++)
            a0 += sw[t] * MV[(size_t)sidx[t] * ND + d];
    }
    // Z = truncated base sum + corrections
    zred[tid] = zacc;
    __syncthreads();
    for (int s = 256; s; s >>= 1) {
        if (tid < s) zred[tid] += zred[tid + s];
        __syncthreads();
    }
    const float Z = zred[0] + zcorr;
    float r = (a0 + a1) + (a2 + a3);
    for (int t = 0; t < i; t++) {
        if (lastf[t]) {
            r += e1s[t] * g_WV[(size_t)t * ND + d] - e0s[t] * MV[(size_t)sl[t] * ND + d];
        }
    }
    g_merged[(size_t)i * (2 * ND) + d] = S[(size_t)i * ND + d];
    g_merged[(size_t)i * (2 * ND) + ND + d] = r / Z;
}

// ---------------- launch ----------------
extern "C" void kernel_launch(void* const* d_in, const int* in_sizes, int n_in,
                              void* d_out, int out_size)
{
    (void)in_sizes; (void)n_in; (void)out_size;
    const float* S  = (const float*)d_in[0];
    const float* MK = (const float*)d_in[1];
    const float* MV = (const float*)d_in[2];
    const float* Wk = (const float*)d_in[3];
    const float* bk = (const float*)d_in[4];
    const float* Wv = (const float*)d_in[5];
    const float* bv = (const float*)d_in[6];
    const float* W1 = (const float*)d_in[7];
    const float* b1 = (const float*)d_in[8];
    const float* W2 = (const float*)d_in[9];
    const float* b2 = (const float*)d_in[10];
    float* out = (float*)d_out;

    float *pK, *pWV, *pG, *pE, *pMerged, *pH1, *pPart;
    cudaGetSymbolAddress((void**)&pK, g_K);
    cudaGetSymbolAddress((void**)&pWV, g_WV);
    cudaGetSymbolAddress((void**)&pG, g_G);
    cudaGetSymbolAddress((void**)&pE, g_E);
    cudaGetSymbolAddress((void**)&pMerged, g_merged);
    cudaGetSymbolAddress((void**)&pH1, g_H1);
    cudaGetSymbolAddress((void**)&pPart, g_part);

    const dim3 blk(256);
    const int MN_KD = NB * ND;      // 131072
    splitk_nt<<<dim3(ND / 64, NB / 64, 4), blk>>>(S, Wk, pPart, ND, ND, ND, 128);
    splitk_nt<<<dim3(ND / 64, NB / 64, 4), blk>>>(S, Wv, pPart + 4 * MN_KD, ND, ND, ND, 128);
    reduce_kernel<<<MN_KD / 1024, blk>>>(pPart, pK, bk, MN_KD, ND, 4, 0);
    reduce_kernel<<<MN_KD / 1024, blk>>>(pPart + 4 * MN_KD, pWV, bv, MN_KD, ND, 4, 0);
    splitk_nt<<<dim3(NB / 64, NB / 64, 4), blk>>>(pK, pK, pPart + 8 * MN_KD, NB, ND, ND, 128);
    reduce_kernel<<<(NB * NB) / 1024, blk>>>(pPart + 8 * MN_KD, pG, nullptr, NB * NB, NB, 4, 0);
    gemm_nt_128<<<dim3(NS / 128, NB / 128), blk>>>(pK, MK, pE, NS, ND);
    prep_kernel<<<NB, 256>>>();
    seq_kernel<<<1, 32>>>();
    passB_kernel<<<NB, 512>>>(S, MV);
    splitk_nt<<<dim3(NH / 64, NB / 64, 2), blk>>>(pMerged, W1, pPart, NH, 2 * ND, 2 * ND, 512);
    reduce_kernel<<<(NB * NH) / 1024, blk>>>(pPart, pH1, b1, NB * NH, NH, 2, 1);
    splitk_nt<<<dim3(ND / 64, NB / 64, 8), blk>>>(pH1, W2, pPart, ND, NH, NH, 256);
    reduce_kernel<<<MN_KD / 1024, blk>>>(pPart, out, b2, MN_KD, ND, 8, 0);
}